// round 15
// baseline (speedup 1.0000x reference)
#include <cuda_runtime.h>

// ---------------- problem constants ----------------
#define PP        0.075f
#define HH        1440
#define WW        1440
#define GZ        32
#define GT        10
#define VZ        0.25f
#define VT        0.05f
#define ZCENTER   4.0f
#define TZCENTER  5.0f
#define CC        64

#define HWC       (HH*WW)                 // 2,073,600
#define W2        (2*HWC/32)              // 129,600 fine words
#define W3        (2*HWC*GZ/32)           // 4,147,200
#define WT        (2*HWC*GT/32)           // 1,296,000
#define OFF2      0
#define OFF3      (W2)
#define OFFT      (W2+W3)
#define TOTW      (W2+W3+WT)              // 5,572,800

// coarse bitmap: 1 bit per fine word; sections padded to 1024-coarse tiles
#define CW2       (W2/32)                 // 4050   (exact)
#define CW3       (W3/32)                 // 129600 (exact)
#define CWT       (WT/32)                 // 40500  (exact)
#define CTILE     1024                    // coarse words per scan tile
#define TC2       4                       // ceil(4050/1024)
#define TC3       127                     // ceil(129600/1024)
#define TCT       40                      // ceil(40500/1024)
#define TOT_CTILES (TC2+TC3+TCT)          // 171
#define CB2       0
#define CB3       (TC2*CTILE)             // 4096
#define CBT       (CB3 + TC3*CTILE)       // 134144
#define CTOT      (CBT + TCT*CTILE)       // 175104

#define FLAG_AGG  (1ULL<<32)
#define FLAG_PRE  (2ULL<<32)

#define PTS       64                       // points per block in point role
#define NUTIL     8                        // util (tailfill) blocks in k_point

// ---------------- scratch (no cudaMalloc allowed) ----------------
// Invariants at entry to kernel_launch:
//   g_bm, g_cm all-zero  (zero-init at load; k_scan zeroes what it consumed)
//   g_ts/g_ticket        reset by k_mark
// g_woff/g_bm2/g_cnt are written-before-read within each run.
__device__ unsigned g_bm[TOTW];           // fine bitmap
__device__ unsigned g_cm[CTOT];           // coarse bitmap (padding never set)
__device__ unsigned g_bm2[TOTW];          // snapshot for rank lookups
__device__ unsigned g_woff[TOTW];         // per-word exclusive rank
__device__ unsigned long long g_ts[TOT_CTILES];
__device__ unsigned g_ticket;
__device__ unsigned g_cnt[3];

// ---------------- key computation ----------------
// XLA folds divide-by-constant into multiply-by-reciprocal (f32 RN folded).
__device__ __forceinline__ void keys_from_vals(float x, float y, float z, float t, int b,
                                               int& k2, int& k3, int& kt,
                                               int& ix, int& iy)
{
    ix = (int)(x * (1.0f/PP));
    iy = (int)(y * (1.0f/PP));
    int iz = (int)(z * (1.0f/VZ));
    int it = (int)(t * (1.0f/VT));
    int base = (b*HH + iy)*WW + ix;
    k2 = base;
    k3 = base*GZ + iz;
    kt = base*GT + it;
}

__device__ __forceinline__ void compute_keys(const float* __restrict__ xyzt,
                                             int i, int c0,
                                             int& k2, int& k3, int& kt,
                                             float& x, float& y, float& z, float& t,
                                             int& ix, int& iy)
{
    x = xyzt[(size_t)i*5+0];
    y = xyzt[(size_t)i*5+1];
    z = xyzt[(size_t)i*5+2];
    t = xyzt[(size_t)i*5+4];
    int b = (i < c0) ? 0 : 1;
    keys_from_vals(x, y, z, t, b, k2, k3, kt, ix, iy);
}

// ---------------- kernels ----------------
// mark: resultless fine+coarse atomicOr (both REDG fire-and-forget).
__global__ __launch_bounds__(256) void k_mark(const float* __restrict__ xyzt,
                                              const int* __restrict__ cnt, int n)
{
    int i = blockIdx.x*256 + threadIdx.x;
    if (i < TOT_CTILES) g_ts[i] = 0ULL;
    if (i == 0) g_ticket = 0u;
    if (i >= n) return;
    int c0 = cnt[0];
    int k2, k3, kt, ix, iy; float x,y,z,t;
    compute_keys(xyzt, i, c0, k2, k3, kt, x, y, z, t, ix, iy);
    int l2 = k2 >> 5, l3 = k3 >> 5, lt = kt >> 5;     // section-local fine word
    atomicOr(&g_bm[OFF2 + l2], 1u << (k2 & 31));
    atomicOr(&g_bm[OFF3 + l3], 1u << (k3 & 31));
    atomicOr(&g_bm[OFFT + lt], 1u << (kt & 31));
    atomicOr(&g_cm[CB2 + (l2 >> 5)], 1u << (l2 & 31));
    atomicOr(&g_cm[CB3 + (l3 >> 5)], 1u << (l3 & 31));
    atomicOr(&g_cm[CBT + (lt >> 5)], 1u << (lt & 31));
}

// coarse-driven scan: per tile (1024 coarse words = up to 32768 fine words),
// gather only NONZERO fine words. Computes per-word rank offsets (woff),
// snapshot (bm2), emits coord rows inline, zeroes consumed fine+coarse words.
__global__ __launch_bounds__(256) void k_scan(float* __restrict__ out, int n)
{
    __shared__ unsigned s_warp[8];
    __shared__ unsigned s_total;
    __shared__ unsigned s_prefix;
    __shared__ unsigned s_tk;

    if (threadIdx.x == 0) s_tk = atomicAdd(&g_ticket, 1u);
    __syncthreads();
    unsigned tk = s_tk;
    if (tk >= TOT_CTILES) return;

    int tile, cb, secw0, stat0, secid, ntiles;
    if (tk < TC2)          { tile = tk;           cb = CB2; secw0 = OFF2; stat0 = 0;       secid = 0; ntiles = TC2; }
    else if (tk < TC2+TC3) { tile = tk - TC2;     cb = CB3; secw0 = OFF3; stat0 = TC2;     secid = 1; ntiles = TC3; }
    else                   { tile = tk - TC2-TC3; cb = CBT; secw0 = OFFT; stat0 = TC2+TC3; secid = 2; ntiles = TCT; }

    int cl0 = tile*CTILE + (int)threadIdx.x*4;    // coarse local (padded space)
    uint4 cv = *reinterpret_cast<const uint4*>(&g_cm[cb + cl0]);
    unsigned cw[4] = {cv.x, cv.y, cv.z, cv.w};

    // pass 1: popcount-sum of referenced fine words
    unsigned tsum = 0;
    #pragma unroll
    for (int j = 0; j < 4; j++) {
        unsigned m = cw[j];
        int flw0 = (cl0 + j) << 5;
        while (m) {
            int b = __ffs(m) - 1; m &= m - 1;
            tsum += __popc(g_bm[secw0 + flw0 + b]);
        }
    }

    // block scan (8 warps)
    unsigned lane = threadIdx.x & 31, wid = threadIdx.x >> 5;
    unsigned incl = tsum;
    #pragma unroll
    for (int o = 1; o < 32; o <<= 1) {
        unsigned v = __shfl_up_sync(0xffffffffu, incl, o);
        if (lane >= (unsigned)o) incl += v;
    }
    if (lane == 31) s_warp[wid] = incl;
    __syncthreads();
    if (wid == 0 && lane < 8) {
        unsigned v = s_warp[lane];
        unsigned si = v;
        #pragma unroll
        for (int o = 1; o < 8; o <<= 1) {
            unsigned tv = __shfl_up_sync(0xffu, si, o);
            if (lane >= (unsigned)o) si += tv;
        }
        s_warp[lane] = si - v;
        if (lane == 7) s_total = si;
    }
    __syncthreads();
    unsigned texcl = incl - tsum + s_warp[wid];
    unsigned agg = s_total;

    // decoupled lookback (warp 0): volatile 64-bit polls + nanosleep backoff
    if (wid == 0) {
        if (tile == 0) {
            if (lane == 0) {
                __threadfence();
                atomicExch(&g_ts[stat0], FLAG_PRE | (unsigned long long)agg);
                s_prefix = 0u;
            }
        } else {
            if (lane == 0) {
                __threadfence();
                atomicExch(&g_ts[stat0 + tile], FLAG_AGG | (unsigned long long)agg);
            }
            unsigned prefix = 0u;
            int idx = tile - 1;
            while (true) {
                int my = idx - (int)lane;
                unsigned long long st = (my >= 0)
                    ? *((volatile unsigned long long*)&g_ts[stat0 + my])
                    : FLAG_PRE;
                unsigned flag = (unsigned)(st >> 32);
                unsigned ready = __ballot_sync(0xffffffffu, flag != 0u);
                if (ready != 0xffffffffu) { __nanosleep(64); continue; }
                unsigned preds = __ballot_sync(0xffffffffu, flag == 2u);
                if (preds) {
                    int fp = __ffs(preds) - 1;
                    unsigned val = (lane <= (unsigned)fp) ? (unsigned)st : 0u;
                    #pragma unroll
                    for (int o = 16; o > 0; o >>= 1)
                        val += __shfl_down_sync(0xffffffffu, val, o);
                    prefix += __shfl_sync(0xffffffffu, val, 0);
                    break;
                } else {
                    unsigned val = (my >= 0) ? (unsigned)st : 0u;
                    #pragma unroll
                    for (int o = 16; o > 0; o >>= 1)
                        val += __shfl_down_sync(0xffffffffu, val, o);
                    prefix += __shfl_sync(0xffffffffu, val, 0);
                    idx -= 32;
                }
            }
            if (lane == 0) {
                __threadfence();
                atomicExch(&g_ts[stat0 + tile],
                           FLAG_PRE | (unsigned long long)(prefix + agg));
                s_prefix = prefix;
            }
        }
    }
    __syncthreads();

    if (threadIdx.x == 0 && tile == ntiles - 1)
        g_cnt[secid] = s_prefix + s_total;

    // pass 2: offsets + snapshot + inline emit + cleanup (gathers are L1-hot)
    unsigned run = s_prefix + texcl;
    size_t O_C3 = (size_t)74*n;
    size_t O_CT = (size_t)149*n;
    #pragma unroll
    for (int j = 0; j < 4; j++) {
        unsigned m = cw[j];
        int flw0 = (cl0 + j) << 5;
        while (m) {
            int b = __ffs(m) - 1; m &= m - 1;
            int flw = flw0 + b;                 // section-local fine word
            int gw = secw0 + flw;
            unsigned fw = g_bm[gw];
            g_woff[gw] = run;
            g_bm2[gw]  = fw;
            g_bm[gw]   = 0u;                    // restore invariant
            unsigned rank = run;
            run += __popc(fw);
            if (secid == 0) {
                while (fw) {
                    int bb = __ffs(fw) - 1; fw &= fw - 1;
                    int v = flw*32 + bb;
                    int pb  = v / HWC;
                    int rem = v % HWC;
                    float* row = out + (size_t)rank*3;
                    row[0] = (float)pb; row[1] = (float)(rem / WW); row[2] = (float)(rem % WW);
                    rank++;
                }
            } else if (secid == 1) {
                while (fw) {
                    int bb = __ffs(fw) - 1; fw &= fw - 1;
                    int v = flw*32 + bb;
                    int vb = v / (HWC*GZ);
                    int r  = v % (HWC*GZ);
                    int vy = r / (WW*GZ);
                    r      = r % (WW*GZ);
                    float* row = out + O_C3 + (size_t)rank*4;
                    row[0] = (float)vb; row[1] = (float)(r % GZ); row[2] = (float)vy; row[3] = (float)(r / GZ);
                    rank++;
                }
            } else {
                while (fw) {
                    int bb = __ffs(fw) - 1; fw &= fw - 1;
                    int v = flw*32 + bb;
                    int tb = v / (HWC*GT);
                    int r  = v % (HWC*GT);
                    int ty = r / (WW*GT);
                    r      = r % (WW*GT);
                    float* row = out + O_CT + (size_t)rank*4;
                    row[0] = (float)tb; row[1] = (float)(r % GT); row[2] = (float)ty; row[3] = (float)(r / GT);
                    rank++;
                }
            }
        }
    }
    // zero own coarse words (uint4 store; padding stays zero)
    *reinterpret_cast<uint4*>(&g_cm[cb + cl0]) = make_uint4(0u,0u,0u,0u);
}

// ---------------- util role: tailfill ----------------
__device__ __forceinline__ void util_role(int uid, float* __restrict__ out, int n)
{
    int gid = uid*256 + (int)threadIdx.x;
    int stride = NUTIL*256;
    unsigned c2 = g_cnt[0], c3 = g_cnt[1], ct = g_cnt[2];
    int lenA = 3*n - 3*(int)c2;
    float* a = out + (size_t)3*c2;
    for (int j = gid; j < lenA; j += stride) a[j] = -1.0f;
    int lenB = 4*n - 4*(int)c3;
    float* bp = out + (size_t)74*n + (size_t)4*c3;
    for (int j = gid; j < lenB; j += stride) bp[j] = -1.0f;
    int lenC = 4*n - 4*(int)ct;
    float* cp = out + (size_t)149*n + (size_t)4*ct;
    for (int j = gid; j < lenC; j += stride) cp[j] = -1.0f;
}

// point kernel: blocks 0..NUTIL-1 = tailfill, rest = 64-point feature blocks
// with in-kernel rank lookups (proven R8 structure; reads bm2 snapshot).
__global__ __launch_bounds__(256, 8) void k_point(const float* __restrict__ xyzt,
                                                  const int* __restrict__ cnt,
                                                  const float* __restrict__ pf,
                                                  float* __restrict__ out, int n)
{
    __shared__ __align__(16) float s_F[PTS*70];
    __shared__ float s_tv[PTS];     // t
    __shared__ float s_td[PTS];     // t - TZCENTER
    __shared__ int   s_k2[PTS], s_k3[PTS], s_kt[PTS];

    int b = blockIdx.x;
    if (b < NUTIL) { util_role(b, out, n); return; }
    int pid = b - NUTIL;

    int i0 = pid * PTS;
    if (i0 >= n) return;
    int npts = n - i0; if (npts > PTS) npts = PTS;
    int tid = threadIdx.x;
    int c0 = cnt[0];

    // stage pf (vector loads, scalar smem stores)
    const float4* pf4 = reinterpret_cast<const float4*>(pf + (size_t)i0*CC);
    for (int u = tid; u < npts*(CC/4); u += 256) {
        float4 v = pf4[u];
        int p = u >> 4;
        int c = (u & 15) * 4;
        float* d = s_F + p*70 + c;
        d[0] = v.x; d[1] = v.y; d[2] = v.z; d[3] = v.w;
    }
    // geometry + keys
    if (tid < npts) {
        int i = i0 + tid;
        int k2, k3, kt, ix, iy; float x,y,z,t;
        compute_keys(xyzt, i, c0, k2, k3, kt, x, y, z, t, ix, iy);
        s_k2[tid] = k2; s_k3[tid] = k3; s_kt[tid] = kt;
        float cx = (ix + 0.5f) * PP;
        float cy = (iy + 0.5f) * PP;
        float* r = s_F + tid*70;
        r[64] = x; r[65] = y; r[66] = z;
        r[67] = x - cx; r[68] = y - cy; r[69] = z - ZCENTER;
        s_tv[tid] = t; s_td[tid] = t - TZCENTER;
    }
    __syncthreads();

    // three rank lookups per point (bm2 snapshot; nothing races it)
    if (tid < 3*npts) {
        int sec = (tid < npts) ? 0 : (tid < 2*npts ? 1 : 2);
        int p = tid - sec*npts;
        int k   = (sec == 0) ? s_k2[p] : (sec == 1) ? s_k3[p] : s_kt[p];
        int off = (sec == 0) ? OFF2 : (sec == 1) ? OFF3 : OFFT;
        size_t dst = (sec == 0) ? (size_t)3*n : (sec == 1) ? (size_t)78*n : (size_t)153*n;
        int w = off + (k >> 5), bb = k & 31;
        unsigned inv = g_woff[w] + (unsigned)__popc(g_bm2[w] & ((1u << bb) - 1u));
        out[dst + i0 + p] = (float)inv;
    }

    int E = npts*70;
    float* fb = out + (size_t)4*n   + (size_t)i0*70;
    float* zb = out + (size_t)79*n  + (size_t)i0*70;
    float* tb = out + (size_t)154*n + (size_t)i0*70;

    if ((n & 3) == 0) {   // all bases 16B-aligned
        const float4* s4 = reinterpret_cast<const float4*>(s_F);
        float4* f4 = reinterpret_cast<float4*>(fb);
        float4* z4 = reinterpret_cast<float4*>(zb);
        float4* t4 = reinterpret_cast<float4*>(tb);
        int E4 = E >> 2;
        for (int u = tid; u < E4; u += 256) {
            float4 v = s4[u];
            f4[u] = v;
            z4[u] = v;
            int e = u << 2;
            int p = e / 70;
            int r = e - p*70;
            if (r == 64)      { v.z = s_tv[p]; }
            else if (r == 66) { v.x = s_tv[p]; v.w = s_td[p]; }
            else if (r == 68) { v.y = s_td[p]; }
            t4[u] = v;
        }
        int rem = E & 3;   // 0 or 2 (70*npts)
        if (rem && tid == 0) {
            int e = E - 2;
            float v0 = s_F[e], v1 = s_F[e+1];
            fb[e] = v0; fb[e+1] = v1;
            zb[e] = v0; zb[e+1] = v1;
            tb[e] = v0; tb[e+1] = s_td[npts-1];
        }
    } else {               // generic scalar fallback
        for (int e = tid; e < E; e += 256) {
            float v = s_F[e];
            fb[e] = v;
            zb[e] = v;
            int p = e / 70;
            int r = e - p*70;
            float vt = (r == 66) ? s_tv[p] : (r == 69) ? s_td[p] : v;
            tb[e] = vt;
        }
    }
}

// ---------------- launch ----------------
extern "C" void kernel_launch(void* const* d_in, const int* in_sizes, int n_in,
                              void* d_out, int out_size)
{
    const float* xyzt = (const float*)d_in[0];
    const int*   cnt  = (const int*)d_in[1];
    const float* pf   = (const float*)d_in[2];
    float*       out  = (float*)d_out;
    int n = in_sizes[0] / 5;

    // 1) mark fine+coarse + state resets
    k_mark<<<(n + 255)/256, 256>>>(xyzt, cnt, n);
    // 2) coarse-driven scan + inline emit + cleanup
    k_scan<<<TOT_CTILES, 256>>>(out, n);
    // 3) point features + ranks + tailfill util role
    {
        int NP = (n + PTS - 1)/PTS;
        k_point<<<NP + NUTIL, 256>>>(xyzt, cnt, pf, out, n);
    }
}

// round 16
// speedup vs baseline: 2.6833x; 2.6833x over previous
#include <cuda_runtime.h>

// ---------------- problem constants ----------------
#define PP        0.075f
#define HH        1440
#define WW        1440
#define GZ        32
#define GT        10
#define VZ        0.25f
#define VT        0.05f
#define ZCENTER   4.0f
#define TZCENTER  5.0f
#define CC        64

#define HWC       (HH*WW)                 // 2,073,600
#define W2        (2*HWC/32)              // 129,600
#define W3        (2*HWC*GZ/32)           // 4,147,200
#define WT        (2*HWC*GT/32)           // 1,296,000
#define OFF2      0
#define OFF3      (W2)
#define OFFT      (W2+W3)
#define TOTW      (W2+W3+WT)              // 5,572,800

// scan tiles: 4096 words per 256-thread scan-role block (16 words / thread)
#define TILE_W    4096
#define WPT       16
#define T2        ((W2+TILE_W-1)/TILE_W)  // 32
#define T3        ((W3+TILE_W-1)/TILE_W)  // 1013
#define TT        ((WT+TILE_W-1)/TILE_W)  // 317
#define TOT_TILES (T2+T3+TT)              // 1362

#define FLAG_AGG  (1ULL<<32)
#define FLAG_PRE  (2ULL<<32)

#define PTS       64                       // points per drain block
#define LISTCAP   600064                   // >= 3*N nonzero words

// ---------------- scratch (no cudaMalloc allowed) ----------------
// Invariants at entry to kernel_launch:
//   g_bm all-zero (zero-init at load; k_final's emit zeroes listed words)
//   g_ts/g_ticket/g_nnz reset by k_mark (before this run's scan role)
__device__ unsigned g_bm[TOTW];
__device__ unsigned g_bm2[TOTW];
__device__ unsigned g_woff[TOTW];
__device__ uint2    g_list[LISTCAP];
__device__ unsigned long long g_ts[TOT_TILES];
__device__ unsigned g_ticket;
__device__ unsigned g_nnz;
__device__ unsigned g_cnt[3];

// ---------------- key computation ----------------
// XLA folds divide-by-constant into multiply-by-reciprocal (f32 RN folded).
__device__ __forceinline__ void keys_from_vals(float x, float y, float z, float t, int b,
                                               int& k2, int& k3, int& kt,
                                               int& ix, int& iy)
{
    ix = (int)(x * (1.0f/PP));
    iy = (int)(y * (1.0f/PP));
    int iz = (int)(z * (1.0f/VZ));
    int it = (int)(t * (1.0f/VT));
    int base = (b*HH + iy)*WW + ix;
    k2 = base;
    k3 = base*GZ + iz;
    kt = base*GT + it;
}

__device__ __forceinline__ void compute_keys(const float* __restrict__ xyzt,
                                             int i, int c0,
                                             int& k2, int& k3, int& kt,
                                             float& x, float& y, float& z, float& t,
                                             int& ix, int& iy)
{
    x = xyzt[(size_t)i*5+0];
    y = xyzt[(size_t)i*5+1];
    z = xyzt[(size_t)i*5+2];
    t = xyzt[(size_t)i*5+4];
    int b = (i < c0) ? 0 : 1;
    keys_from_vals(x, y, z, t, b, k2, k3, kt, ix, iy);
}

// ---------------- kernels ----------------
// mark: 2 points/thread, all loads issued before atomics (MLP), resultless
// atomicOr (REDG fire-and-forget) + state resets.
__global__ __launch_bounds__(256) void k_mark(const float* __restrict__ xyzt,
                                              const int* __restrict__ cnt, int n)
{
    int g = blockIdx.x*256 + threadIdx.x;
    if (g < TOT_TILES) g_ts[g] = 0ULL;
    if (g == 0) { g_ticket = 0u; g_nnz = 0u; }
    int i0 = g*2;
    if (i0 >= n) return;
    int c0 = cnt[0];
    int i1 = i0 + 1;
    bool has1 = i1 < n;

    float x0 = xyzt[(size_t)i0*5+0];
    float y0 = xyzt[(size_t)i0*5+1];
    float z0 = xyzt[(size_t)i0*5+2];
    float t0 = xyzt[(size_t)i0*5+4];
    float x1 = has1 ? xyzt[(size_t)i1*5+0] : 0.f;
    float y1 = has1 ? xyzt[(size_t)i1*5+1] : 0.f;
    float z1 = has1 ? xyzt[(size_t)i1*5+2] : 0.f;
    float t1 = has1 ? xyzt[(size_t)i1*5+4] : 0.f;

    int k2a, k3a, kta, ixa, iya;
    keys_from_vals(x0, y0, z0, t0, (i0 < c0) ? 0 : 1, k2a, k3a, kta, ixa, iya);
    atomicOr(&g_bm[OFF2 + (k2a >> 5)], 1u << (k2a & 31));
    atomicOr(&g_bm[OFF3 + (k3a >> 5)], 1u << (k3a & 31));
    atomicOr(&g_bm[OFFT + (kta >> 5)], 1u << (kta & 31));
    if (has1) {
        int k2b, k3b, ktb, ixb, iyb;
        keys_from_vals(x1, y1, z1, t1, (i1 < c0) ? 0 : 1, k2b, k3b, ktb, ixb, iyb);
        atomicOr(&g_bm[OFF2 + (k2b >> 5)], 1u << (k2b & 31));
        atomicOr(&g_bm[OFF3 + (k3b >> 5)], 1u << (k3b & 31));
        atomicOr(&g_bm[OFFT + (ktb >> 5)], 1u << (ktb & 31));
    }
}

// ---------------- scan role (256 threads, ticket + decoupled lookback) ----
__device__ void scan_role()
{
    __shared__ unsigned s_warp[8];
    __shared__ unsigned s_total;
    __shared__ unsigned s_prefix;
    __shared__ unsigned s_tk;

    if (threadIdx.x == 0) s_tk = atomicAdd(&g_ticket, 1u);
    __syncthreads();
    unsigned tk = s_tk;
    if (tk >= TOT_TILES) return;          // extra taker, ticket unused

    int tile, secw0, words, stat0, secid, ntiles;
    if (tk < T2)           { tile = tk;           secw0 = OFF2; words = W2; stat0 = 0;     secid = 0; ntiles = T2; }
    else if (tk < T2+T3)   { tile = tk - T2;      secw0 = OFF3; words = W3; stat0 = T2;    secid = 1; ntiles = T3; }
    else                   { tile = tk - T2 - T3; secw0 = OFFT; words = WT; stat0 = T2+T3; secid = 2; ntiles = TT; }

    int base_w = tile*TILE_W + (int)threadIdx.x*WPT;
    unsigned bw[WPT];
    unsigned tsum = 0;
    #pragma unroll
    for (int q = 0; q < 4; q++) {
        int off = base_w + q*4;                   // section sizes are mod-4
        if (off < words) {
            uint4 v = *reinterpret_cast<const uint4*>(&g_bm[secw0 + off]);
            bw[q*4+0] = v.x; bw[q*4+1] = v.y; bw[q*4+2] = v.z; bw[q*4+3] = v.w;
        } else {
            bw[q*4+0] = bw[q*4+1] = bw[q*4+2] = bw[q*4+3] = 0u;
        }
        tsum += __popc(bw[q*4+0]) + __popc(bw[q*4+1]) + __popc(bw[q*4+2]) + __popc(bw[q*4+3]);
    }

    unsigned lane = threadIdx.x & 31, wid = threadIdx.x >> 5;
    unsigned incl = tsum;
    #pragma unroll
    for (int o = 1; o < 32; o <<= 1) {
        unsigned v = __shfl_up_sync(0xffffffffu, incl, o);
        if (lane >= (unsigned)o) incl += v;
    }
    if (lane == 31) s_warp[wid] = incl;
    __syncthreads();
    if (wid == 0 && lane < 8) {
        unsigned v = s_warp[lane];
        unsigned si = v;
        #pragma unroll
        for (int o = 1; o < 8; o <<= 1) {
            unsigned tv = __shfl_up_sync(0xffu, si, o);
            if (lane >= (unsigned)o) si += tv;
        }
        s_warp[lane] = si - v;
        if (lane == 7) s_total = si;
    }
    __syncthreads();
    unsigned texcl = incl - tsum + s_warp[wid];
    unsigned agg = s_total;

    // decoupled lookback (warp 0): volatile 64-bit polls + nanosleep backoff
    if (wid == 0) {
        if (tile == 0) {
            if (lane == 0) {
                __threadfence();
                atomicExch(&g_ts[stat0], FLAG_PRE | (unsigned long long)agg);
                s_prefix = 0u;
            }
        } else {
            if (lane == 0) {
                __threadfence();
                atomicExch(&g_ts[stat0 + tile], FLAG_AGG | (unsigned long long)agg);
            }
            unsigned prefix = 0u;
            int idx = tile - 1;
            while (true) {
                int my = idx - (int)lane;
                unsigned long long st = (my >= 0)
                    ? *((volatile unsigned long long*)&g_ts[stat0 + my])
                    : FLAG_PRE;
                unsigned flag = (unsigned)(st >> 32);
                unsigned ready = __ballot_sync(0xffffffffu, flag != 0u);
                if (ready != 0xffffffffu) { __nanosleep(64); continue; }
                unsigned preds = __ballot_sync(0xffffffffu, flag == 2u);
                if (preds) {
                    int fp = __ffs(preds) - 1;
                    unsigned val = (lane <= (unsigned)fp) ? (unsigned)st : 0u;
                    #pragma unroll
                    for (int o = 16; o > 0; o >>= 1)
                        val += __shfl_down_sync(0xffffffffu, val, o);
                    prefix += __shfl_sync(0xffffffffu, val, 0);
                    break;
                } else {
                    unsigned val = (my >= 0) ? (unsigned)st : 0u;
                    #pragma unroll
                    for (int o = 16; o > 0; o >>= 1)
                        val += __shfl_down_sync(0xffffffffu, val, o);
                    prefix += __shfl_sync(0xffffffffu, val, 0);
                    idx -= 32;
                }
            }
            if (lane == 0) {
                __threadfence();
                atomicExch(&g_ts[stat0 + tile],
                           FLAG_PRE | (unsigned long long)(prefix + agg));
                s_prefix = prefix;
            }
        }
    }
    __syncthreads();

    if (threadIdx.x == 0 && tile == ntiles - 1)
        g_cnt[secid] = s_prefix + s_total;

    // predicated per-word offsets + snapshot + unordered list
    unsigned run = s_prefix + texcl;
    unsigned mycnt = 0;
    #pragma unroll
    for (int j = 0; j < WPT; j++) {
        if (base_w + j < words && bw[j]) {
            g_woff[secw0 + base_w + j] = run;
            g_bm2[secw0 + base_w + j]  = bw[j];
            mycnt++;
        }
        run += __popc(bw[j]);
    }
    unsigned cincl = mycnt;
    #pragma unroll
    for (int o = 1; o < 32; o <<= 1) {
        unsigned v = __shfl_up_sync(0xffffffffu, cincl, o);
        if (lane >= (unsigned)o) cincl += v;
    }
    unsigned wtot = __shfl_sync(0xffffffffu, cincl, 31);
    unsigned lbase = 0;
    if (lane == 0 && wtot) lbase = atomicAdd(&g_nnz, wtot);
    lbase = __shfl_sync(0xffffffffu, lbase, 0);
    unsigned pos = lbase + cincl - mycnt;
    #pragma unroll
    for (int j = 0; j < WPT; j++) {
        if (base_w + j < words && bw[j]) {
            g_list[pos] = make_uint2((unsigned)(secw0 + base_w + j), bw[j]);
            pos++;
        }
    }
}

// k_mid: interleaved roles. b%3==0 -> scan role (ticketed, no dependence on
// drain); else drain role pid = b - b/3 - 1 (bijective onto 0..NP-1).
// Drain uses streaming cache hints (output never re-read in-kernel).
__global__ __launch_bounds__(256, 8) void k_mid(const float* __restrict__ xyzt,
                                                const int* __restrict__ cnt,
                                                const float* __restrict__ pf,
                                                float* __restrict__ out, int n)
{
    __shared__ __align__(16) float s_F[PTS*70];
    __shared__ float s_tv[PTS];
    __shared__ float s_td[PTS];

    int b = blockIdx.x;
    if (b % 3 == 0) { scan_role(); return; }
    int pid = b - b/3 - 1;

    int i0 = pid * PTS;
    if (i0 >= n) return;
    int npts = n - i0; if (npts > PTS) npts = PTS;
    int tid = threadIdx.x;
    int c0 = cnt[0];

    // stage pf (streaming loads)
    const float4* pf4 = reinterpret_cast<const float4*>(pf + (size_t)i0*CC);
    for (int u = tid; u < npts*(CC/4); u += 256) {
        float4 v = __ldcs(&pf4[u]);
        int p = u >> 4;
        int c = (u & 15) * 4;
        float* d = s_F + p*70 + c;
        d[0] = v.x; d[1] = v.y; d[2] = v.z; d[3] = v.w;
    }
    // geometry
    if (tid < npts) {
        int i = i0 + tid;
        int k2, k3, kt, ix, iy; float x,y,z,t;
        compute_keys(xyzt, i, c0, k2, k3, kt, x, y, z, t, ix, iy);
        float cx = (ix + 0.5f) * PP;
        float cy = (iy + 0.5f) * PP;
        float* r = s_F + tid*70;
        r[64] = x; r[65] = y; r[66] = z;
        r[67] = x - cx; r[68] = y - cy; r[69] = z - ZCENTER;
        s_tv[tid] = t; s_td[tid] = t - TZCENTER;
    }
    __syncthreads();

    int E = npts*70;
    float* fb = out + (size_t)4*n   + (size_t)i0*70;
    float* zb = out + (size_t)79*n  + (size_t)i0*70;
    float* tb = out + (size_t)154*n + (size_t)i0*70;

    if ((n & 3) == 0) {
        const float4* s4 = reinterpret_cast<const float4*>(s_F);
        float4* f4 = reinterpret_cast<float4*>(fb);
        float4* z4 = reinterpret_cast<float4*>(zb);
        float4* t4 = reinterpret_cast<float4*>(tb);
        int E4 = E >> 2;
        for (int u = tid; u < E4; u += 256) {
            float4 v = s4[u];
            __stcs(&f4[u], v);
            __stcs(&z4[u], v);
            int e = u << 2;
            int p = e / 70;
            int r = e - p*70;
            if (r == 64)      { v.z = s_tv[p]; }
            else if (r == 66) { v.x = s_tv[p]; v.w = s_td[p]; }
            else if (r == 68) { v.y = s_td[p]; }
            __stcs(&t4[u], v);
        }
        int rem = E & 3;   // 0 or 2
        if (rem && tid == 0) {
            int e = E - 2;
            float v0 = s_F[e], v1 = s_F[e+1];
            fb[e] = v0; fb[e+1] = v1;
            zb[e] = v0; zb[e+1] = v1;
            tb[e] = v0; tb[e+1] = s_td[npts-1];
        }
    } else {
        for (int e = tid; e < E; e += 256) {
            float v = s_F[e];
            fb[e] = v;
            zb[e] = v;
            int p = e / 70;
            int r = e - p*70;
            float vt = (r == 66) ? s_tv[p] : (r == 69) ? s_td[p] : v;
            tb[e] = vt;
        }
    }
}

// k_final: per-point ranks + list-driven emit (+bm cleanup) + tailfill.
__global__ __launch_bounds__(256) void k_final(const float* __restrict__ xyzt,
                                               const int* __restrict__ cnt,
                                               float* __restrict__ out, int n)
{
    int gid = blockIdx.x*256 + threadIdx.x;
    int stride = gridDim.x*256;
    int c0 = cnt[0];

    // ranks
    for (int i = gid; i < n; i += stride) {
        int k2, k3, kt, ix, iy; float x,y,z,t;
        compute_keys(xyzt, i, c0, k2, k3, kt, x, y, z, t, ix, iy);
        int w2 = OFF2 + (k2 >> 5), b2 = k2 & 31;
        int w3 = OFF3 + (k3 >> 5), b3 = k3 & 31;
        int wt = OFFT + (kt >> 5), bt = kt & 31;
        unsigned i2 = g_woff[w2] + (unsigned)__popc(g_bm2[w2] & ((1u << b2) - 1u));
        unsigned i3 = g_woff[w3] + (unsigned)__popc(g_bm2[w3] & ((1u << b3) - 1u));
        unsigned it = g_woff[wt] + (unsigned)__popc(g_bm2[wt] & ((1u << bt) - 1u));
        out[(size_t)3*n   + i] = (float)i2;
        out[(size_t)78*n  + i] = (float)i3;
        out[(size_t)153*n + i] = (float)it;
    }

    // tail fill
    {
        unsigned c2 = g_cnt[0], c3 = g_cnt[1], ct = g_cnt[2];
        int lenA = 3*n - 3*(int)c2;
        float* a = out + (size_t)3*c2;
        for (int j = gid; j < lenA; j += stride) a[j] = -1.0f;
        int lenB = 4*n - 4*(int)c3;
        float* bp = out + (size_t)74*n + (size_t)4*c3;
        for (int j = gid; j < lenB; j += stride) bp[j] = -1.0f;
        int lenC = 4*n - 4*(int)ct;
        float* cp = out + (size_t)149*n + (size_t)4*ct;
        for (int j = gid; j < lenC; j += stride) cp[j] = -1.0f;
    }

    // list-driven emit + bitmap cleanup
    size_t O_C3 = (size_t)74*n;
    size_t O_CT = (size_t)149*n;
    int nnz = (int)g_nnz;
    for (int e = gid; e < nnz; e += stride) {
        uint2 ent = g_list[e];
        int w = (int)ent.x;
        unsigned m = ent.y;
        g_bm[w] = 0u;
        unsigned rank = g_woff[w];
        if (w < OFF3) {
            while (m) {
                int bb = __ffs(m) - 1; m &= m - 1;
                int v = w*32 + bb;
                int pb  = v / HWC;
                int rem = v % HWC;
                float* row = out + (size_t)rank*3;
                row[0] = (float)pb; row[1] = (float)(rem / WW); row[2] = (float)(rem % WW);
                rank++;
            }
        } else if (w < OFFT) {
            int wl = w - OFF3;
            while (m) {
                int bb = __ffs(m) - 1; m &= m - 1;
                int v = wl*32 + bb;
                int vb = v / (HWC*GZ);
                int r  = v % (HWC*GZ);
                int vy = r / (WW*GZ);
                r      = r % (WW*GZ);
                float* row = out + O_C3 + (size_t)rank*4;
                row[0] = (float)vb; row[1] = (float)(r % GZ); row[2] = (float)vy; row[3] = (float)(r / GZ);
                rank++;
            }
        } else {
            int wl = w - OFFT;
            while (m) {
                int bb = __ffs(m) - 1; m &= m - 1;
                int v = wl*32 + bb;
                int tb = v / (HWC*GT);
                int r  = v % (HWC*GT);
                int ty = r / (WW*GT);
                r      = r % (WW*GT);
                float* row = out + O_CT + (size_t)rank*4;
                row[0] = (float)tb; row[1] = (float)(r % GT); row[2] = (float)ty; row[3] = (float)(r / GT);
                rank++;
            }
        }
    }
}

// ---------------- launch ----------------
extern "C" void kernel_launch(void* const* d_in, const int* in_sizes, int n_in,
                              void* d_out, int out_size)
{
    const float* xyzt = (const float*)d_in[0];
    const int*   cnt  = (const int*)d_in[1];
    const float* pf   = (const float*)d_in[2];
    float*       out  = (float*)d_out;
    int n = in_sizes[0] / 5;

    // 1) mark + state resets (2 pts/thread)
    {
        int nb = (n/2 + 256)/256 + 1;
        int need = (TOT_TILES + 255)/256;
        if (nb < need) nb = need;
        k_mark<<<nb, 256>>>(xyzt, cnt, n);
    }
    // 2) scan role || feature-drain role in one launch
    {
        int NP = (n + PTS - 1)/PTS;                 // drain blocks needed
        int T = (3*NP + 1)/2;                       // ceil(NP*3/2)
        while (T - (T + 2)/3 < NP) T++;
        int nscan = (T + 2)/3;
        if (nscan < TOT_TILES) T = NP + TOT_TILES;  // fallback (won't trigger here)
        k_mid<<<T, 256>>>(xyzt, cnt, pf, out, n);
    }
    // 3) ranks + emit + tailfill
    k_final<<<2048, 256>>>(xyzt, cnt, out, n);
}

// round 17
// speedup vs baseline: 2.6844x; 1.0004x over previous
#include <cuda_runtime.h>

// ---------------- problem constants ----------------
#define PP        0.075f
#define HH        1440
#define WW        1440
#define GZ        32
#define GT        10
#define VZ        0.25f
#define VT        0.05f
#define ZCENTER   4.0f
#define TZCENTER  5.0f
#define CC        64

#define HWC       (HH*WW)                 // 2,073,600
#define W2        (2*HWC/32)              // 129,600
#define W3        (2*HWC*GZ/32)           // 4,147,200
#define WT        (2*HWC*GT/32)           // 1,296,000
#define OFF2      0
#define OFF3      (W2)
#define OFFT      (W2+W3)
#define TOTW      (W2+W3+WT)              // 5,572,800

// scan tiles: 4096 words per 256-thread scan-role block (16 words / thread)
#define TILE_W    4096
#define WPT       16
#define T2        ((W2+TILE_W-1)/TILE_W)  // 32
#define T3        ((W3+TILE_W-1)/TILE_W)  // 1013
#define TT        ((WT+TILE_W-1)/TILE_W)  // 317
#define TOT_TILES (T2+T3+TT)              // 1362

#define FLAG_AGG  (1ULL<<32)
#define FLAG_PRE  (2ULL<<32)

#define PTS       64                       // points per drain block
#define LISTCAP   600064                   // >= 3*N nonzero words

// ---------------- scratch (no cudaMalloc allowed) ----------------
// Invariants at entry to kernel_launch:
//   g_bm all-zero (zero-init at load; k_final's emit zeroes listed words)
//   g_ts/g_ticket/g_nnz reset by k_mark (before this run's scan role)
__device__ unsigned g_bm[TOTW];
__device__ unsigned g_bm2[TOTW];
__device__ unsigned g_woff[TOTW];
__device__ uint2    g_list[LISTCAP];
__device__ unsigned long long g_ts[TOT_TILES];
__device__ unsigned g_ticket;
__device__ unsigned g_nnz;
__device__ unsigned g_cnt[3];

// ---------------- key computation ----------------
// XLA folds divide-by-constant into multiply-by-reciprocal (f32 RN folded).
__device__ __forceinline__ void keys_from_vals(float x, float y, float z, float t, int b,
                                               int& k2, int& k3, int& kt,
                                               int& ix, int& iy)
{
    ix = (int)(x * (1.0f/PP));
    iy = (int)(y * (1.0f/PP));
    int iz = (int)(z * (1.0f/VZ));
    int it = (int)(t * (1.0f/VT));
    int base = (b*HH + iy)*WW + ix;
    k2 = base;
    k3 = base*GZ + iz;
    kt = base*GT + it;
}

__device__ __forceinline__ void compute_keys(const float* __restrict__ xyzt,
                                             int i, int c0,
                                             int& k2, int& k3, int& kt,
                                             float& x, float& y, float& z, float& t,
                                             int& ix, int& iy)
{
    x = xyzt[(size_t)i*5+0];
    y = xyzt[(size_t)i*5+1];
    z = xyzt[(size_t)i*5+2];
    t = xyzt[(size_t)i*5+4];
    int b = (i < c0) ? 0 : 1;
    keys_from_vals(x, y, z, t, b, k2, k3, kt, ix, iy);
}

// ---------------- kernels ----------------
// mark: 2 points/thread, streaming loads issued before atomics, resultless
// atomicOr (REDG fire-and-forget) + state resets.
__global__ __launch_bounds__(256) void k_mark(const float* __restrict__ xyzt,
                                              const int* __restrict__ cnt, int n)
{
    int g = blockIdx.x*256 + threadIdx.x;
    if (g < TOT_TILES) g_ts[g] = 0ULL;
    if (g == 0) { g_ticket = 0u; g_nnz = 0u; }
    int i0 = g*2;
    if (i0 >= n) return;
    int c0 = cnt[0];
    int i1 = i0 + 1;
    bool has1 = i1 < n;

    float x0 = __ldcs(&xyzt[(size_t)i0*5+0]);
    float y0 = __ldcs(&xyzt[(size_t)i0*5+1]);
    float z0 = __ldcs(&xyzt[(size_t)i0*5+2]);
    float t0 = __ldcs(&xyzt[(size_t)i0*5+4]);
    float x1 = has1 ? __ldcs(&xyzt[(size_t)i1*5+0]) : 0.f;
    float y1 = has1 ? __ldcs(&xyzt[(size_t)i1*5+1]) : 0.f;
    float z1 = has1 ? __ldcs(&xyzt[(size_t)i1*5+2]) : 0.f;
    float t1 = has1 ? __ldcs(&xyzt[(size_t)i1*5+4]) : 0.f;

    int k2a, k3a, kta, ixa, iya;
    keys_from_vals(x0, y0, z0, t0, (i0 < c0) ? 0 : 1, k2a, k3a, kta, ixa, iya);
    atomicOr(&g_bm[OFF2 + (k2a >> 5)], 1u << (k2a & 31));
    atomicOr(&g_bm[OFF3 + (k3a >> 5)], 1u << (k3a & 31));
    atomicOr(&g_bm[OFFT + (kta >> 5)], 1u << (kta & 31));
    if (has1) {
        int k2b, k3b, ktb, ixb, iyb;
        keys_from_vals(x1, y1, z1, t1, (i1 < c0) ? 0 : 1, k2b, k3b, ktb, ixb, iyb);
        atomicOr(&g_bm[OFF2 + (k2b >> 5)], 1u << (k2b & 31));
        atomicOr(&g_bm[OFF3 + (k3b >> 5)], 1u << (k3b & 31));
        atomicOr(&g_bm[OFFT + (ktb >> 5)], 1u << (ktb & 31));
    }
}

// ---------------- scan role (256 threads, ticket + decoupled lookback) ----
__device__ void scan_role()
{
    __shared__ unsigned s_warp[8];
    __shared__ unsigned s_total;
    __shared__ unsigned s_prefix;
    __shared__ unsigned s_tk;

    if (threadIdx.x == 0) s_tk = atomicAdd(&g_ticket, 1u);
    __syncthreads();
    unsigned tk = s_tk;
    if (tk >= TOT_TILES) return;          // extra taker, ticket unused

    int tile, secw0, words, stat0, secid, ntiles;
    if (tk < T2)           { tile = tk;           secw0 = OFF2; words = W2; stat0 = 0;     secid = 0; ntiles = T2; }
    else if (tk < T2+T3)   { tile = tk - T2;      secw0 = OFF3; words = W3; stat0 = T2;    secid = 1; ntiles = T3; }
    else                   { tile = tk - T2 - T3; secw0 = OFFT; words = WT; stat0 = T2+T3; secid = 2; ntiles = TT; }

    int base_w = tile*TILE_W + (int)threadIdx.x*WPT;
    unsigned bw[WPT];
    unsigned tsum = 0;
    #pragma unroll
    for (int q = 0; q < 4; q++) {
        int off = base_w + q*4;                   // section sizes are mod-4
        if (off < words) {
            // read-once: evict-first so L2 keeps woff/bm2/list for k_final
            uint4 v = __ldcs(reinterpret_cast<const uint4*>(&g_bm[secw0 + off]));
            bw[q*4+0] = v.x; bw[q*4+1] = v.y; bw[q*4+2] = v.z; bw[q*4+3] = v.w;
        } else {
            bw[q*4+0] = bw[q*4+1] = bw[q*4+2] = bw[q*4+3] = 0u;
        }
        tsum += __popc(bw[q*4+0]) + __popc(bw[q*4+1]) + __popc(bw[q*4+2]) + __popc(bw[q*4+3]);
    }

    unsigned lane = threadIdx.x & 31, wid = threadIdx.x >> 5;
    unsigned incl = tsum;
    #pragma unroll
    for (int o = 1; o < 32; o <<= 1) {
        unsigned v = __shfl_up_sync(0xffffffffu, incl, o);
        if (lane >= (unsigned)o) incl += v;
    }
    if (lane == 31) s_warp[wid] = incl;
    __syncthreads();
    if (wid == 0 && lane < 8) {
        unsigned v = s_warp[lane];
        unsigned si = v;
        #pragma unroll
        for (int o = 1; o < 8; o <<= 1) {
            unsigned tv = __shfl_up_sync(0xffu, si, o);
            if (lane >= (unsigned)o) si += tv;
        }
        s_warp[lane] = si - v;
        if (lane == 7) s_total = si;
    }
    __syncthreads();
    unsigned texcl = incl - tsum + s_warp[wid];
    unsigned agg = s_total;

    // decoupled lookback (warp 0): volatile 64-bit polls + nanosleep backoff
    if (wid == 0) {
        if (tile == 0) {
            if (lane == 0) {
                __threadfence();
                atomicExch(&g_ts[stat0], FLAG_PRE | (unsigned long long)agg);
                s_prefix = 0u;
            }
        } else {
            if (lane == 0) {
                __threadfence();
                atomicExch(&g_ts[stat0 + tile], FLAG_AGG | (unsigned long long)agg);
            }
            unsigned prefix = 0u;
            int idx = tile - 1;
            while (true) {
                int my = idx - (int)lane;
                unsigned long long st = (my >= 0)
                    ? *((volatile unsigned long long*)&g_ts[stat0 + my])
                    : FLAG_PRE;
                unsigned flag = (unsigned)(st >> 32);
                unsigned ready = __ballot_sync(0xffffffffu, flag != 0u);
                if (ready != 0xffffffffu) { __nanosleep(64); continue; }
                unsigned preds = __ballot_sync(0xffffffffu, flag == 2u);
                if (preds) {
                    int fp = __ffs(preds) - 1;
                    unsigned val = (lane <= (unsigned)fp) ? (unsigned)st : 0u;
                    #pragma unroll
                    for (int o = 16; o > 0; o >>= 1)
                        val += __shfl_down_sync(0xffffffffu, val, o);
                    prefix += __shfl_sync(0xffffffffu, val, 0);
                    break;
                } else {
                    unsigned val = (my >= 0) ? (unsigned)st : 0u;
                    #pragma unroll
                    for (int o = 16; o > 0; o >>= 1)
                        val += __shfl_down_sync(0xffffffffu, val, o);
                    prefix += __shfl_sync(0xffffffffu, val, 0);
                    idx -= 32;
                }
            }
            if (lane == 0) {
                __threadfence();
                atomicExch(&g_ts[stat0 + tile],
                           FLAG_PRE | (unsigned long long)(prefix + agg));
                s_prefix = prefix;
            }
        }
    }
    __syncthreads();

    if (threadIdx.x == 0 && tile == ntiles - 1)
        g_cnt[secid] = s_prefix + s_total;

    // predicated per-word offsets + snapshot + unordered list
    unsigned run = s_prefix + texcl;
    unsigned mycnt = 0;
    #pragma unroll
    for (int j = 0; j < WPT; j++) {
        if (base_w + j < words && bw[j]) {
            g_woff[secw0 + base_w + j] = run;
            g_bm2[secw0 + base_w + j]  = bw[j];
            mycnt++;
        }
        run += __popc(bw[j]);
    }
    unsigned cincl = mycnt;
    #pragma unroll
    for (int o = 1; o < 32; o <<= 1) {
        unsigned v = __shfl_up_sync(0xffffffffu, cincl, o);
        if (lane >= (unsigned)o) cincl += v;
    }
    unsigned wtot = __shfl_sync(0xffffffffu, cincl, 31);
    unsigned lbase = 0;
    if (lane == 0 && wtot) lbase = atomicAdd(&g_nnz, wtot);
    lbase = __shfl_sync(0xffffffffu, lbase, 0);
    unsigned pos = lbase + cincl - mycnt;
    #pragma unroll
    for (int j = 0; j < WPT; j++) {
        if (base_w + j < words && bw[j]) {
            g_list[pos] = make_uint2((unsigned)(secw0 + base_w + j), bw[j]);
            pos++;
        }
    }
}

// k_mid: interleaved roles. b%3==0 -> scan role (ticketed, no dependence on
// drain); else drain role pid = b - b/3 - 1 (bijective onto 0..NP-1).
// Drain uses streaming cache hints (output never re-read in-kernel).
__global__ __launch_bounds__(256, 8) void k_mid(const float* __restrict__ xyzt,
                                                const int* __restrict__ cnt,
                                                const float* __restrict__ pf,
                                                float* __restrict__ out, int n)
{
    __shared__ __align__(16) float s_F[PTS*70];
    __shared__ float s_tv[PTS];
    __shared__ float s_td[PTS];

    int b = blockIdx.x;
    if (b % 3 == 0) { scan_role(); return; }
    int pid = b - b/3 - 1;

    int i0 = pid * PTS;
    if (i0 >= n) return;
    int npts = n - i0; if (npts > PTS) npts = PTS;
    int tid = threadIdx.x;
    int c0 = cnt[0];

    // stage pf (streaming loads)
    const float4* pf4 = reinterpret_cast<const float4*>(pf + (size_t)i0*CC);
    for (int u = tid; u < npts*(CC/4); u += 256) {
        float4 v = __ldcs(&pf4[u]);
        int p = u >> 4;
        int c = (u & 15) * 4;
        float* d = s_F + p*70 + c;
        d[0] = v.x; d[1] = v.y; d[2] = v.z; d[3] = v.w;
    }
    // geometry
    if (tid < npts) {
        int i = i0 + tid;
        int k2, k3, kt, ix, iy; float x,y,z,t;
        compute_keys(xyzt, i, c0, k2, k3, kt, x, y, z, t, ix, iy);
        float cx = (ix + 0.5f) * PP;
        float cy = (iy + 0.5f) * PP;
        float* r = s_F + tid*70;
        r[64] = x; r[65] = y; r[66] = z;
        r[67] = x - cx; r[68] = y - cy; r[69] = z - ZCENTER;
        s_tv[tid] = t; s_td[tid] = t - TZCENTER;
    }
    __syncthreads();

    int E = npts*70;
    float* fb = out + (size_t)4*n   + (size_t)i0*70;
    float* zb = out + (size_t)79*n  + (size_t)i0*70;
    float* tb = out + (size_t)154*n + (size_t)i0*70;

    if ((n & 3) == 0) {
        const float4* s4 = reinterpret_cast<const float4*>(s_F);
        float4* f4 = reinterpret_cast<float4*>(fb);
        float4* z4 = reinterpret_cast<float4*>(zb);
        float4* t4 = reinterpret_cast<float4*>(tb);
        int E4 = E >> 2;
        for (int u = tid; u < E4; u += 256) {
            float4 v = s4[u];
            __stcs(&f4[u], v);
            __stcs(&z4[u], v);
            int e = u << 2;
            int p = e / 70;
            int r = e - p*70;
            if (r == 64)      { v.z = s_tv[p]; }
            else if (r == 66) { v.x = s_tv[p]; v.w = s_td[p]; }
            else if (r == 68) { v.y = s_td[p]; }
            __stcs(&t4[u], v);
        }
        int rem = E & 3;   // 0 or 2
        if (rem && tid == 0) {
            int e = E - 2;
            float v0 = s_F[e], v1 = s_F[e+1];
            fb[e] = v0; fb[e+1] = v1;
            zb[e] = v0; zb[e+1] = v1;
            tb[e] = v0; tb[e+1] = s_td[npts-1];
        }
    } else {
        for (int e = tid; e < E; e += 256) {
            float v = s_F[e];
            fb[e] = v;
            zb[e] = v;
            int p = e / 70;
            int r = e - p*70;
            float vt = (r == 66) ? s_tv[p] : (r == 69) ? s_td[p] : v;
            tb[e] = vt;
        }
    }
}

// k_final: per-point ranks + list-driven emit (+bm cleanup) + tailfill.
// All output writes streamed; list read-once streamed.
__global__ __launch_bounds__(256) void k_final(const float* __restrict__ xyzt,
                                               const int* __restrict__ cnt,
                                               float* __restrict__ out, int n)
{
    int gid = blockIdx.x*256 + threadIdx.x;
    int stride = gridDim.x*256;
    int c0 = cnt[0];

    // ranks
    for (int i = gid; i < n; i += stride) {
        int k2, k3, kt, ix, iy; float x,y,z,t;
        compute_keys(xyzt, i, c0, k2, k3, kt, x, y, z, t, ix, iy);
        int w2 = OFF2 + (k2 >> 5), b2 = k2 & 31;
        int w3 = OFF3 + (k3 >> 5), b3 = k3 & 31;
        int wt = OFFT + (kt >> 5), bt = kt & 31;
        unsigned i2 = g_woff[w2] + (unsigned)__popc(g_bm2[w2] & ((1u << b2) - 1u));
        unsigned i3 = g_woff[w3] + (unsigned)__popc(g_bm2[w3] & ((1u << b3) - 1u));
        unsigned it = g_woff[wt] + (unsigned)__popc(g_bm2[wt] & ((1u << bt) - 1u));
        __stcs(&out[(size_t)3*n   + i], (float)i2);
        __stcs(&out[(size_t)78*n  + i], (float)i3);
        __stcs(&out[(size_t)153*n + i], (float)it);
    }

    // tail fill
    {
        unsigned c2 = g_cnt[0], c3 = g_cnt[1], ct = g_cnt[2];
        int lenA = 3*n - 3*(int)c2;
        float* a = out + (size_t)3*c2;
        for (int j = gid; j < lenA; j += stride) __stcs(&a[j], -1.0f);
        int lenB = 4*n - 4*(int)c3;
        float* bp = out + (size_t)74*n + (size_t)4*c3;
        for (int j = gid; j < lenB; j += stride) __stcs(&bp[j], -1.0f);
        int lenC = 4*n - 4*(int)ct;
        float* cp = out + (size_t)149*n + (size_t)4*ct;
        for (int j = gid; j < lenC; j += stride) __stcs(&cp[j], -1.0f);
    }

    // list-driven emit + bitmap cleanup
    size_t O_C3 = (size_t)74*n;
    size_t O_CT = (size_t)149*n;
    int nnz = (int)g_nnz;
    for (int e = gid; e < nnz; e += stride) {
        uint2 ent = __ldcs(&g_list[e]);
        int w = (int)ent.x;
        unsigned m = ent.y;
        g_bm[w] = 0u;
        unsigned rank = g_woff[w];
        if (w < OFF3) {
            while (m) {
                int bb = __ffs(m) - 1; m &= m - 1;
                int v = w*32 + bb;
                int pb  = v / HWC;
                int rem = v % HWC;
                float* row = out + (size_t)rank*3;
                __stcs(&row[0], (float)pb);
                __stcs(&row[1], (float)(rem / WW));
                __stcs(&row[2], (float)(rem % WW));
                rank++;
            }
        } else if (w < OFFT) {
            int wl = w - OFF3;
            while (m) {
                int bb = __ffs(m) - 1; m &= m - 1;
                int v = wl*32 + bb;
                int vb = v / (HWC*GZ);
                int r  = v % (HWC*GZ);
                int vy = r / (WW*GZ);
                r      = r % (WW*GZ);
                float* row = out + O_C3 + (size_t)rank*4;
                __stcs(&row[0], (float)vb);
                __stcs(&row[1], (float)(r % GZ));
                __stcs(&row[2], (float)vy);
                __stcs(&row[3], (float)(r / GZ));
                rank++;
            }
        } else {
            int wl = w - OFFT;
            while (m) {
                int bb = __ffs(m) - 1; m &= m - 1;
                int v = wl*32 + bb;
                int tb = v / (HWC*GT);
                int r  = v % (HWC*GT);
                int ty = r / (WW*GT);
                r      = r % (WW*GT);
                float* row = out + O_CT + (size_t)rank*4;
                __stcs(&row[0], (float)tb);
                __stcs(&row[1], (float)(r % GT));
                __stcs(&row[2], (float)ty);
                __stcs(&row[3], (float)(r / GT));
                rank++;
            }
        }
    }
}

// ---------------- launch ----------------
extern "C" void kernel_launch(void* const* d_in, const int* in_sizes, int n_in,
                              void* d_out, int out_size)
{
    const float* xyzt = (const float*)d_in[0];
    const int*   cnt  = (const int*)d_in[1];
    const float* pf   = (const float*)d_in[2];
    float*       out  = (float*)d_out;
    int n = in_sizes[0] / 5;

    // 1) mark + state resets (2 pts/thread)
    {
        int nb = (n/2 + 256)/256 + 1;
        int need = (TOT_TILES + 255)/256;
        if (nb < need) nb = need;
        k_mark<<<nb, 256>>>(xyzt, cnt, n);
    }
    // 2) scan role || feature-drain role in one launch
    {
        int NP = (n + PTS - 1)/PTS;                 // drain blocks needed
        int T = (3*NP + 1)/2;                       // ceil(NP*3/2)
        while (T - (T + 2)/3 < NP) T++;
        int nscan = (T + 2)/3;
        if (nscan < TOT_TILES) T = NP + TOT_TILES;  // fallback (won't trigger here)
        k_mid<<<T, 256>>>(xyzt, cnt, pf, out, n);
    }
    // 3) ranks + emit + tailfill
    k_final<<<2048, 256>>>(xyzt, cnt, out, n);
}